// round 7
// baseline (speedup 1.0000x reference)
#include <cuda_runtime.h>
#include <stdint.h>

#define D_DIM      1024
#define D4         256            // float4s per row
#define TPB        256
#define RPI        8              // rows per tile (= warps per CTA)
#define NSTAGE     3
#define NBLK       296            // 148 SMs * 2 CTAs, persistent
#define TILE_BYTES (RPI * D_DIM * 4)        // 32768
#define ROW_BYTES  (D_DIM * 4)              // 4096
#define C4_OFF     (NSTAGE * TILE_BYTES)    // 98304
#define RED_OFF    (C4_OFF + 4096)          // 102400
#define MBAR_OFF   (RED_OFF + 2 * 8 * 32 * 4) // 104448
#define SMEM_BYTES (MBAR_OFF + 64)

__device__ __forceinline__ float dot4(float4 a, float4 b) {
    return fmaf(a.x, b.x, fmaf(a.y, b.y, fmaf(a.z, b.z, a.w * b.w)));
}

// ---- 1-D TMA bulk + mbarrier primitives ----
__device__ __forceinline__ void mbar_init(uint32_t mbar, uint32_t count) {
    asm volatile("mbarrier.init.shared.b64 [%0], %1;" :: "r"(mbar), "r"(count) : "memory");
}
__device__ __forceinline__ void mbar_expect_tx(uint32_t mbar, uint32_t bytes) {
    asm volatile("mbarrier.arrive.expect_tx.shared.b64 _, [%0], %1;"
                 :: "r"(mbar), "r"(bytes) : "memory");
}
__device__ __forceinline__ void mbar_wait(uint32_t mbar, uint32_t parity) {
    uint32_t done;
    asm volatile("{\n\t.reg .pred p;\n\t"
                 "mbarrier.try_wait.parity.acquire.cta.shared::cta.b64 p, [%1], %2;\n\t"
                 "selp.b32 %0, 1, 0, p;\n\t}"
                 : "=r"(done) : "r"(mbar), "r"(parity) : "memory");
    if (!done) {
        asm volatile("{\n\t.reg .pred P1;\n\t"
                     "W_%=:\n\t"
                     "mbarrier.try_wait.parity.acquire.cta.shared::cta.b64 P1, [%0], %1, 0x989680;\n\t"
                     "@P1 bra.uni D_%=;\n\t"
                     "bra.uni W_%=;\n\t"
                     "D_%=:\n\t}"
                     :: "r"(mbar), "r"(parity) : "memory");
    }
}
__device__ __forceinline__ void bulk_load(uint32_t smem_dst, const void* gsrc,
                                          uint32_t bytes, uint32_t mbar) {
    asm volatile("cp.async.bulk.shared::cluster.global.mbarrier::complete_tx::bytes "
                 "[%0], [%1], %2, [%3];"
                 :: "r"(smem_dst), "l"(gsrc), "r"(bytes), "r"(mbar) : "memory");
}
__device__ __forceinline__ void bulk_store(void* gdst, uint32_t smem_src, uint32_t bytes) {
    asm volatile("cp.async.bulk.global.shared::cta.bulk_group [%0], [%1], %2;"
                 :: "l"(gdst), "r"(smem_src), "r"(bytes) : "memory");
}
__device__ __forceinline__ void bulk_commit() {
    asm volatile("cp.async.bulk.commit_group;" ::: "memory");
}
__device__ __forceinline__ void bulk_wait_read0() {
    asm volatile("cp.async.bulk.wait_group.read 0;" ::: "memory");
}
__device__ __forceinline__ void bulk_wait_all0() {
    asm volatile("cp.async.bulk.wait_group 0;" ::: "memory");
}
__device__ __forceinline__ void fence_async_shared() {
    asm volatile("fence.proxy.async.shared::cta;" ::: "memory");
}

extern "C" __global__ void __launch_bounds__(TPB, 2)
cross_kernel(const float4* __restrict__ x4,
             const float4* __restrict__ w4,
             const float4* __restrict__ b4,
             float*        __restrict__ outp,
             int n_rows) {
    extern __shared__ char smem_raw[];
    float4* c4smem = reinterpret_cast<float4*>(smem_raw + C4_OFF);   // [256]
    float*  red    = reinterpret_cast<float*>(smem_raw + RED_OFF);   // [2][8][32]

    const int tid  = threadIdx.x;
    const int warp = tid >> 5;
    const int lane = tid & 31;
    const uint32_t smem_u32 = (uint32_t)__cvta_generic_to_shared(smem_raw);
    const uint32_t mbar0    = smem_u32 + MBAR_OFF;

    const int ntiles = n_rows / RPI;          // 2048
    const int grid   = gridDim.x;
    const int tile0  = blockIdx.x;

    // ---- mbarrier init ----
    if (tid == 0) {
        mbar_init(mbar0 + 0, 1);
        mbar_init(mbar0 + 8, 1);
        mbar_init(mbar0 + 16, 1);
    }

    // ---- prologue: weights in regs, c4/g reduction ----
    const float4 w0 = w4[tid];
    const float4 w1 = w4[D4 + tid];
    const float4 w2 = w4[2 * D4 + tid];
    const float4 w3 = w4[3 * D4 + tid];
    const float4 b0 = b4[tid];
    const float4 b1 = b4[D4 + tid];
    const float4 b2 = b4[2 * D4 + tid];
    const float4 b3 = b4[3 * D4 + tid];

    float4 c1, c2, c3, c4v;
    c1 = b0;
    c2.x = c1.x + b1.x; c2.y = c1.y + b1.y; c2.z = c1.z + b1.z; c2.w = c1.w + b1.w;
    c3.x = c2.x + b2.x; c3.y = c2.y + b2.y; c3.z = c2.z + b2.z; c3.w = c2.w + b2.w;
    c4v.x = c3.x + b3.x; c4v.y = c3.y + b3.y; c4v.z = c3.z + b3.z; c4v.w = c3.w + b3.w;
    c4smem[tid] = c4v;

    float h1 = dot4(c1, w1);
    float h2 = dot4(c2, w2);
    float h3 = dot4(c3, w3);
    #pragma unroll
    for (int off = 16; off > 0; off >>= 1) {
        h1 += __shfl_xor_sync(0xffffffffu, h1, off);
        h2 += __shfl_xor_sync(0xffffffffu, h2, off);
        h3 += __shfl_xor_sync(0xffffffffu, h3, off);
    }
    if (lane == 0) {
        red[warp * 32 + 0] = h1; red[warp * 32 + 1] = h2; red[warp * 32 + 2] = h3;
    }
    __syncthreads();   // mbar init + c4smem + red visible

    float gg1 = 0.0f, gg2 = 0.0f, gg3 = 0.0f;
    #pragma unroll
    for (int wi = 0; wi < 8; wi++) {
        gg1 += red[wi * 32 + 0]; gg2 += red[wi * 32 + 1]; gg3 += red[wi * 32 + 2];
    }
    // per-lane c4 for phase-2 row layout: float4 index = lane + 32*j
    float4 c4p2[8];
    #pragma unroll
    for (int j = 0; j < 8; j++) c4p2[j] = c4smem[lane + 32 * j];

    // prime the TMA ring (stages 0,1)
    if (tid == 0) {
        #pragma unroll
        for (int s = 0; s < NSTAGE - 1; s++) {
            const int t = tile0 + s * grid;
            if (t < ntiles) {
                mbar_expect_tx(mbar0 + s * 8, TILE_BYTES);
                bulk_load(smem_u32 + s * TILE_BYTES,
                          (const char*)x4 + (size_t)t * TILE_BYTES,
                          TILE_BYTES, mbar0 + s * 8);
            }
        }
    }
    __syncthreads();   // gg/c4p2 reads done before loop writes red

    // ---- main loop ----
    int s = 0, par = 0, it = 0;
    for (int k = tile0; k < ntiles; k += grid, ++it) {
        // drain my warp's previous bulk store (smem read) before the barrier
        if (lane == 0) bulk_wait_read0();

        mbar_wait(mbar0 + s * 8, (uint32_t)par);

        // phase 1: dots, column tid across 8 rows
        const float4* st = reinterpret_cast<const float4*>(
            smem_raw + s * TILE_BYTES) + tid;
        float vals[32];
        #pragma unroll
        for (int r = 0; r < RPI; r++) {
            float4 xr = st[r * D4];
            vals[r * 4 + 0] = dot4(xr, w0);
            vals[r * 4 + 1] = dot4(xr, w1);
            vals[r * 4 + 2] = dot4(xr, w2);
            vals[r * 4 + 3] = dot4(xr, w3);
        }
        #pragma unroll
        for (int o = 16; o >= 1; o >>= 1) {
            #pragma unroll
            for (int i = 0; i < o; i++) {
                float send  = (lane & o) ? vals[i] : vals[i + o];
                float other = __shfl_xor_sync(0xffffffffu, send, o);
                vals[i] = ((lane & o) ? vals[i + o] : vals[i]) + other;
            }
        }
        const int rp = it & 1;
        red[(rp * 8 + warp) * 32 + lane] = vals[0];
        __syncthreads();

        // thread 0: prefetch tile k+2*grid into stage (s+2)%3
        if (tid == 0) {
            const int tl = k + (NSTAGE - 1) * grid;
            if (tl < ntiles) {
                int sl = s + (NSTAGE - 1); if (sl >= NSTAGE) sl -= NSTAGE;
                mbar_expect_tx(mbar0 + sl * 8, TILE_BYTES);
                bulk_load(smem_u32 + sl * TILE_BYTES,
                          (const char*)x4 + (size_t)tl * TILE_BYTES,
                          TILE_BYTES, mbar0 + sl * 8);
            }
        }

        // combine (redundant per warp)
        float tot = red[(rp * 8 + 0) * 32 + lane];
        #pragma unroll
        for (int wi = 1; wi < 8; wi++)
            tot += red[(rp * 8 + wi) * 32 + lane];
        const int rbase4 = lane & ~3;
        float p0 = __shfl_sync(0xffffffffu, tot, rbase4 + 0);
        float p1 = __shfl_sync(0xffffffffu, tot, rbase4 + 1);
        float p2 = __shfl_sync(0xffffffffu, tot, rbase4 + 2);
        float p3 = __shfl_sync(0xffffffffu, tot, rbase4 + 3);
        float a = 1.0f;
        a = fmaf(a, p0, a);            // g0 = 0
        a = fmaf(a, p1, a + gg1);
        a = fmaf(a, p2, a + gg2);
        a = fmaf(a, p3, a + gg3);
        const float a_w = __shfl_sync(0xffffffffu, a, warp << 2);

        // phase 2: warp w rewrites row w of the stage in place, TMA-stores it
        float4* rowp = reinterpret_cast<float4*>(
            smem_raw + s * TILE_BYTES + warp * ROW_BYTES) + lane;
        #pragma unroll
        for (int j = 0; j < 8; j++) {
            float4 xr = rowp[j * 32];
            float4 o;
            o.x = fmaf(xr.x, a_w, c4p2[j].x);
            o.y = fmaf(xr.y, a_w, c4p2[j].y);
            o.z = fmaf(xr.z, a_w, c4p2[j].z);
            o.w = fmaf(xr.w, a_w, c4p2[j].w);
            rowp[j * 32] = o;
        }
        fence_async_shared();
        __syncwarp();
        if (lane == 0) {
            bulk_store(outp + ((size_t)k * RPI + warp) * D_DIM,
                       smem_u32 + s * TILE_BYTES + warp * ROW_BYTES,
                       ROW_BYTES);
            bulk_commit();
        }

        if (++s == NSTAGE) { s = 0; par ^= 1; }
    }

    // make sure all bulk stores are fully complete before exit
    if (lane == 0) bulk_wait_all0();
}

extern "C" void kernel_launch(void* const* d_in, const int* in_sizes, int n_in,
                              void* d_out, int out_size) {
    const float* x = (const float*)d_in[0];
    const float* w = (const float*)d_in[1];
    const float* b = (const float*)d_in[2];
    float* out = (float*)d_out;

    int n_rows = in_sizes[0] / D_DIM;  // 16384

    cudaFuncSetAttribute(cross_kernel,
                         cudaFuncAttributeMaxDynamicSharedMemorySize, SMEM_BYTES);
    cross_kernel<<<NBLK, TPB, SMEM_BYTES>>>(
        (const float4*)x, (const float4*)w, (const float4*)b,
        out, n_rows);
}